// round 1
// baseline (speedup 1.0000x reference)
#include <cuda_runtime.h>
#include <math.h>

#define B_ROWS   4096
#define D_DIM    256
#define N_TOT    8192            // 2B
#define INV_T    (1.0f / 0.07f)

#define BM 128
#define BN 128
#define BK 16
#define COL_SPLITS 2
#define COLS_PER_BLOCK (N_TOT / COL_SPLITS)   // 4096

// Scratch (allocation-free rule: __device__ globals)
__device__ float g_zn[N_TOT * D_DIM];          // normalized rows, f32
__device__ float g_pos[B_ROWS];                // zi_n . zj_n per pair
__device__ float g_rowsum[COL_SPLITS * N_TOT]; // partial sum of exp((sim-1)/T), j != i

// ---------------------------------------------------------------------------
// 1) L2-normalize both inputs into g_zn. One warp per row (256 elems, 8/lane).
// ---------------------------------------------------------------------------
__global__ void normalize_kernel(const float* __restrict__ zi,
                                 const float* __restrict__ zj) {
    int warp = (blockIdx.x * blockDim.x + threadIdx.x) >> 5;
    int lane = threadIdx.x & 31;
    if (warp >= N_TOT) return;
    const float* src = (warp < B_ROWS) ? (zi + (size_t)warp * D_DIM)
                                       : (zj + (size_t)(warp - B_ROWS) * D_DIM);
    float v[8];
    float ss = 0.f;
#pragma unroll
    for (int i = 0; i < 8; i++) {
        v[i] = src[lane + 32 * i];
        ss += v[i] * v[i];
    }
#pragma unroll
    for (int off = 16; off > 0; off >>= 1)
        ss += __shfl_xor_sync(0xffffffffu, ss, off);
    float inv = 1.0f / sqrtf(ss);
    float* dst = g_zn + (size_t)warp * D_DIM;
#pragma unroll
    for (int i = 0; i < 8; i++)
        dst[lane + 32 * i] = v[i] * inv;
}

// ---------------------------------------------------------------------------
// 2) pos[i] = dot(zn_i, zn_{i+B}). One warp per pair.
// ---------------------------------------------------------------------------
__global__ void pos_kernel() {
    int warp = (blockIdx.x * blockDim.x + threadIdx.x) >> 5;
    int lane = threadIdx.x & 31;
    if (warp >= B_ROWS) return;
    const float* a = g_zn + (size_t)warp * D_DIM;
    const float* b = g_zn + (size_t)(warp + B_ROWS) * D_DIM;
    float s = 0.f;
#pragma unroll
    for (int i = 0; i < 8; i++)
        s += a[lane + 32 * i] * b[lane + 32 * i];
#pragma unroll
    for (int off = 16; off > 0; off >>= 1)
        s += __shfl_xor_sync(0xffffffffu, s, off);
    if (lane == 0) g_pos[warp] = s;
}

// ---------------------------------------------------------------------------
// 3) Fused GEMM_NT + exp + row-sum.
//    Grid (N_TOT/BM, COL_SPLITS). Block: 256 threads, 128x128 tile, 8x8 micro.
//    Micro-tile split as {ty*4..+3, 64+ty*4..+3} x {tx*4..+3, 64+tx*4..+3}
//    so shared loads are contiguous float4s (conflict-free-ish).
// ---------------------------------------------------------------------------
__global__ void __launch_bounds__(256) simexp_kernel() {
    __shared__ float As[BK][BM];
    __shared__ float Bs[BK][BN];
    __shared__ float Red[BM][17];   // padded partial row sums

    const int tid = threadIdx.x;
    const int tx = tid & 15;
    const int ty = tid >> 4;
    const int rowBase = blockIdx.x * BM;
    const int colStart = blockIdx.y * COLS_PER_BLOCK;

    float rsum[8];
#pragma unroll
    for (int i = 0; i < 8; i++) rsum[i] = 0.f;

    for (int ct = 0; ct < COLS_PER_BLOCK; ct += BN) {
        const int colBase = colStart + ct;
        float acc[8][8];
#pragma unroll
        for (int i = 0; i < 8; i++)
#pragma unroll
            for (int j = 0; j < 8; j++) acc[i][j] = 0.f;

        for (int k0 = 0; k0 < D_DIM; k0 += BK) {
            // Load 128x16 A tile and 128x16 B tile (transposed into [k][row]).
#pragma unroll
            for (int r = 0; r < 2; r++) {
                int e   = tid * 2 + r;        // float4 index 0..511
                int row = e >> 2;             // 4 float4 per row
                int kk  = (e & 3) << 2;
                float4 va = *(const float4*)(g_zn + (size_t)(rowBase + row) * D_DIM + k0 + kk);
                As[kk + 0][row] = va.x; As[kk + 1][row] = va.y;
                As[kk + 2][row] = va.z; As[kk + 3][row] = va.w;
                float4 vb = *(const float4*)(g_zn + (size_t)(colBase + row) * D_DIM + k0 + kk);
                Bs[kk + 0][row] = vb.x; Bs[kk + 1][row] = vb.y;
                Bs[kk + 2][row] = vb.z; Bs[kk + 3][row] = vb.w;
            }
            __syncthreads();

#pragma unroll
            for (int k = 0; k < BK; k++) {
                float a[8], b[8];
                *(float4*)&a[0] = *(const float4*)&As[k][ty * 4];
                *(float4*)&a[4] = *(const float4*)&As[k][64 + ty * 4];
                *(float4*)&b[0] = *(const float4*)&Bs[k][tx * 4];
                *(float4*)&b[4] = *(const float4*)&Bs[k][64 + tx * 4];
#pragma unroll
                for (int i = 0; i < 8; i++)
#pragma unroll
                    for (int j = 0; j < 8; j++)
                        acc[i][j] = fmaf(a[i], b[j], acc[i][j]);
            }
            __syncthreads();
        }

        // Epilogue: exp((s-1)/T), skip diagonal, accumulate per-row sums.
#pragma unroll
        for (int i = 0; i < 8; i++) {
            int lrow = (i < 4) ? (ty * 4 + i) : (64 + ty * 4 + i - 4);
            int grow = rowBase + lrow;
            float acc_r = 0.f;
#pragma unroll
            for (int j = 0; j < 8; j++) {
                int lcol = (j < 4) ? (tx * 4 + j) : (64 + tx * 4 + j - 4);
                int gcol = colBase + lcol;
                float e = __expf(fmaf(acc[i][j], INV_T, -INV_T));
                acc_r += (grow == gcol) ? 0.f : e;
            }
            rsum[i] += acc_r;
        }
    }

    // Reduce the 16 column-partials per row inside the block; one clean store.
    __syncthreads();
#pragma unroll
    for (int i = 0; i < 8; i++) {
        int lrow = (i < 4) ? (ty * 4 + i) : (64 + ty * 4 + i - 4);
        Red[lrow][tx] = rsum[i];
    }
    __syncthreads();
    if (tid < BM) {
        float s = 0.f;
#pragma unroll
        for (int t = 0; t < 16; t++) s += Red[tid][t];
        g_rowsum[blockIdx.y * N_TOT + rowBase + tid] = s;   // written exactly once
    }
}

// ---------------------------------------------------------------------------
// 4) per_row = 1/T + log(S_i) - pos[i mod B]/T ; out = mean
// ---------------------------------------------------------------------------
__global__ void finalize_kernel(float* __restrict__ out) {
    __shared__ float sdata[256];
    int tid = threadIdx.x;
    float s = 0.f;
    for (int i = tid; i < N_TOT; i += 256) {
        float S = g_rowsum[i] + g_rowsum[N_TOT + i];
        float p = g_pos[i & (B_ROWS - 1)];
        s += INV_T + logf(S) - p * INV_T;
    }
    sdata[tid] = s;
    __syncthreads();
    for (int off = 128; off > 0; off >>= 1) {
        if (tid < off) sdata[tid] += sdata[tid + off];
        __syncthreads();
    }
    if (tid == 0) out[0] = sdata[0] / (float)N_TOT;
}

// ---------------------------------------------------------------------------
extern "C" void kernel_launch(void* const* d_in, const int* in_sizes, int n_in,
                              void* d_out, int out_size) {
    (void)in_sizes; (void)n_in; (void)out_size;
    const float* zi = (const float*)d_in[0];
    const float* zj = (const float*)d_in[1];

    normalize_kernel<<<N_TOT / 8, 256>>>(zi, zj);   // 8 warps/block
    pos_kernel<<<B_ROWS / 8, 256>>>();
    dim3 grid(N_TOT / BM, COL_SPLITS);              // (64, 2)
    simexp_kernel<<<grid, 256>>>();
    finalize_kernel<<<1, 256>>>((float*)d_out);
}

// round 3
// speedup vs baseline: 9.1763x; 9.1763x over previous
#include <cuda_runtime.h>
#include <cuda_bf16.h>
#include <cstdint>

#define B_ROWS 4096
#define N_TOT  8192
#define D_DIM  256
#define INV_T  14.285714285714285714f
#define LOG2E  1.44269504088896340736f
#define LN2    0.69314718055994530942f
#define C1F    (INV_T * LOG2E)

// ---------------- device scratch (no allocs allowed) ----------------
__device__ __nv_bfloat16 g_zn[N_TOT * D_DIM];   // normalized rows, bf16, 4MB
__device__ float g_pos[B_ROWS];
__device__ float g_rowsum[4 * N_TOT];           // [colHalf*2 + wn][row]

// ---------------- PTX helpers (compute_100-safe only) ----------------
__device__ __forceinline__ uint32_t smem_u32(const void* p) {
    uint32_t a;
    asm("{ .reg .u64 t; cvta.to.shared.u64 t, %1; cvt.u32.u64 %0, t; }" : "=r"(a) : "l"(p));
    return a;
}
#define CP_ASYNC_CG(sm, gp) \
    asm volatile("cp.async.cg.shared.global [%0], [%1], 16;" :: "r"(sm), "l"(gp))
#define CP_COMMIT()   asm volatile("cp.async.commit_group;" ::: "memory")
#define CP_WAIT_ALL() asm volatile("cp.async.wait_group 0;" ::: "memory")

#define LDSM_X4(r0, r1, r2, r3, addr) \
    asm volatile("ldmatrix.sync.aligned.m8n8.x4.shared.b16 {%0,%1,%2,%3}, [%4];" \
                 : "=r"(r0), "=r"(r1), "=r"(r2), "=r"(r3) : "r"(addr))

__device__ __forceinline__ void mma_bf16(float* c, uint32_t a0, uint32_t a1,
                                         uint32_t a2, uint32_t a3,
                                         uint32_t b0, uint32_t b1) {
    asm volatile(
        "mma.sync.aligned.m16n8k16.row.col.f32.bf16.bf16.f32 "
        "{%0,%1,%2,%3}, {%4,%5,%6,%7}, {%8,%9}, {%0,%1,%2,%3};"
        : "+f"(c[0]), "+f"(c[1]), "+f"(c[2]), "+f"(c[3])
        : "r"(a0), "r"(a1), "r"(a2), "r"(a3), "r"(b0), "r"(b1));
}

__device__ __forceinline__ float expx(float d) {
    float x = fmaf(d, C1F, -C1F);
    float e;
    asm("ex2.approx.f32 %0, %1;" : "=f"(e) : "f"(x));
    return e;
}

// ---------------------------------------------------------------------------
// 1) Fused normalize + pos: one warp per pair i. Writes bf16 rows i and B+i.
// ---------------------------------------------------------------------------
__global__ void norm_pos_kernel(const float* __restrict__ zi,
                                const float* __restrict__ zj) {
    int w = (blockIdx.x * blockDim.x + threadIdx.x) >> 5;
    int lane = threadIdx.x & 31;
    if (w >= B_ROWS) return;
    const float4* pa = (const float4*)(zi + (size_t)w * D_DIM);
    const float4* pb = (const float4*)(zj + (size_t)w * D_DIM);
    float4 a0 = pa[lane * 2], a1 = pa[lane * 2 + 1];
    float4 b0 = pb[lane * 2], b1 = pb[lane * 2 + 1];
    float sa = a0.x*a0.x + a0.y*a0.y + a0.z*a0.z + a0.w*a0.w
             + a1.x*a1.x + a1.y*a1.y + a1.z*a1.z + a1.w*a1.w;
    float sb = b0.x*b0.x + b0.y*b0.y + b0.z*b0.z + b0.w*b0.w
             + b1.x*b1.x + b1.y*b1.y + b1.z*b1.z + b1.w*b1.w;
    float sd = a0.x*b0.x + a0.y*b0.y + a0.z*b0.z + a0.w*b0.w
             + a1.x*b1.x + a1.y*b1.y + a1.z*b1.z + a1.w*b1.w;
#pragma unroll
    for (int off = 16; off > 0; off >>= 1) {
        sa += __shfl_xor_sync(0xffffffffu, sa, off);
        sb += __shfl_xor_sync(0xffffffffu, sb, off);
        sd += __shfl_xor_sync(0xffffffffu, sd, off);
    }
    float ia = rsqrtf(sa), ib = rsqrtf(sb);
    if (lane == 0) g_pos[w] = sd * ia * ib;

    uint32_t* da = (uint32_t*)(g_zn + (size_t)w * D_DIM);
    uint32_t* db = (uint32_t*)(g_zn + (size_t)(w + B_ROWS) * D_DIM);
    __nv_bfloat162 t;
    t = __floats2bfloat162_rn(a0.x*ia, a0.y*ia); da[lane*4+0] = *(uint32_t*)&t;
    t = __floats2bfloat162_rn(a0.z*ia, a0.w*ia); da[lane*4+1] = *(uint32_t*)&t;
    t = __floats2bfloat162_rn(a1.x*ia, a1.y*ia); da[lane*4+2] = *(uint32_t*)&t;
    t = __floats2bfloat162_rn(a1.z*ia, a1.w*ia); da[lane*4+3] = *(uint32_t*)&t;
    t = __floats2bfloat162_rn(b0.x*ib, b0.y*ib); db[lane*4+0] = *(uint32_t*)&t;
    t = __floats2bfloat162_rn(b0.z*ib, b0.w*ib); db[lane*4+1] = *(uint32_t*)&t;
    t = __floats2bfloat162_rn(b1.x*ib, b1.y*ib); db[lane*4+2] = *(uint32_t*)&t;
    t = __floats2bfloat162_rn(b1.z*ib, b1.w*ib); db[lane*4+3] = *(uint32_t*)&t;
}

// ---------------------------------------------------------------------------
// 2) Fused warp-MMA GEMM + exp + row-sum.
// SMEM: A[64KB] | B0[64KB] | B1[64KB].  Each 128x256 bf16 tile is stored as
// 4 chunks of [128 rows x 64 cols] with 128B rows and SW128 XOR swizzle.
// ---------------------------------------------------------------------------
#define A_OFF    0u
#define B0_OFF   65536u
#define B1_OFF   131072u
#define SMEM_REQ 196608

// All 256 threads cooperatively cp.async one 64KB tile (4096 x 16B).
__device__ __forceinline__ void load_tile256(int rowG, uint32_t dst, int tid) {
#pragma unroll
    for (int p = 0; p < 16; p++) {
        int i = tid + p * 256;
        int chunk = i >> 10, rem = i & 1023, row = rem >> 3, seg = rem & 7;
        const __nv_bfloat16* g = g_zn + (size_t)(rowG + row) * D_DIM + chunk * 64 + seg * 8;
        uint32_t soff = (uint32_t)(row * 128 + seg * 16);
        soff ^= (soff >> 3) & 0x70;
        CP_ASYNC_CG(dst + chunk * 16384u + soff, g);
    }
}

__global__ void __launch_bounds__(256, 1) sim_kernel() {
    extern __shared__ char dsm[];
    const uint32_t sbase = smem_u32(dsm);
    const uint32_t sA = sbase + A_OFF;
    const uint32_t sB[2] = { sbase + B0_OFF, sbase + B1_OFF };

    const int tid = threadIdx.x, wid = tid >> 5, lane = tid & 31;
    const int wm = wid & 3, wn = wid >> 2;            // 4 x 2 warp grid
    const int rowBase = blockIdx.x * 128;
    const int colHalf = blockIdx.y;

    // ldmatrix per-lane addressing: mat = lane>>3 (0..3), rowIn = lane&7
    // mat0:{+0,k}, mat1:{+8,k}, mat2:{+0,k+8}, mat3:{+8,k+8}
    const int mat = lane >> 3, rowIn = lane & 7;
    const int rsel = (mat & 1) << 3;                  // +0 / +8 rows
    const int ksel = (mat >> 1) << 3;                 // +0 / +8 k-elems (16B)

    // Precompute row-dependent parts. addr = base_m + chunk*16384 + (kb ^ swm)
    // where kb = in-chunk k byte offset, swm = (m&7)<<4.
    const int mA0 = wm * 32 + rsel + rowIn;           // mt adds +16
    const int nB0 = wn * 64 + rsel + rowIn;           // nt adds +16
    uint32_t aBase[2], aSw[2], bBase[4], bSw[4];
#pragma unroll
    for (int mt = 0; mt < 2; mt++) {
        int m = mA0 + mt * 16;
        aBase[mt] = sA + (uint32_t)(m * 128);
        aSw[mt] = (uint32_t)((m & 7) << 4);
    }
#pragma unroll
    for (int nt = 0; nt < 4; nt++) {
        int n = nB0 + nt * 16;
        bBase[nt] = (uint32_t)(n * 128);              // + sB[buf] at use
        bSw[nt] = (uint32_t)((n & 7) << 4);
    }

    // Prologue: A tile + first B tile in one cp.async group.
    load_tile256(rowBase, sA, tid);
    load_tile256(colHalf * 4096, sB[0], tid);
    CP_COMMIT();

    float rs[2][2] = {{0.f, 0.f}, {0.f, 0.f}};

#pragma unroll 1
    for (int t = 0; t < 32; t++) {
        const int buf = t & 1;
        CP_WAIT_ALL();
        __syncthreads();
        if (t < 31) {
            load_tile256(colHalf * 4096 + (t + 1) * 128, sB[buf ^ 1], tid);
            CP_COMMIT();
        }

        float acc[2][8][4];
#pragma unroll
        for (int i = 0; i < 2; i++)
#pragma unroll
            for (int j = 0; j < 8; j++)
#pragma unroll
                for (int q = 0; q < 4; q++) acc[i][j][q] = 0.f;

        const uint32_t sBt = sB[buf];
#pragma unroll
        for (int ks = 0; ks < 16; ks++) {
            const uint32_t chunkOff = (uint32_t)(ks >> 2) * 16384u;
            const uint32_t kb = (uint32_t)(((ks & 3) * 16 + ksel) * 2);
            uint32_t a[2][4];
#pragma unroll
            for (int mt = 0; mt < 2; mt++)
                LDSM_X4(a[mt][0], a[mt][1], a[mt][2], a[mt][3],
                        aBase[mt] + chunkOff + (kb ^ aSw[mt]));
#pragma unroll
            for (int nt = 0; nt < 4; nt++) {
                uint32_t b0, b1, b2, b3;
                LDSM_X4(b0, b1, b2, b3,
                        sBt + bBase[nt] + chunkOff + (kb ^ bSw[nt]));
                // r0:n0-7/k0-7, r1:n8-15/k0-7, r2:n0-7/k8-15, r3:n8-15/k8-15
#pragma unroll
                for (int mt = 0; mt < 2; mt++) {
                    mma_bf16(acc[mt][2 * nt],     a[mt][0], a[mt][1], a[mt][2], a[mt][3], b0, b2);
                    mma_bf16(acc[mt][2 * nt + 1], a[mt][0], a[mt][1], a[mt][2], a[mt][3], b1, b3);
                }
            }
        }

        // Epilogue: exp2((d-1)*C1), skip diagonal, accumulate row-sums in regs.
        const int colT = colHalf * 4096 + t * 128 + wn * 64;
        const int rA0 = rowBase + wm * 32 + (lane >> 2);
#pragma unroll
        for (int mt = 0; mt < 2; mt++) {
            const int rA = rA0 + mt * 16;     // rows for c0,c1
            const int rB = rA + 8;            // rows for c2,c3
            float s0 = 0.f, s1 = 0.f;
#pragma unroll
            for (int nt = 0; nt < 8; nt++) {
                const int cg = colT + nt * 8 + ((lane & 3) << 1);
                float e0 = expx(acc[mt][nt][0]);
                float e1 = expx(acc[mt][nt][1]);
                float e2 = expx(acc[mt][nt][2]);
                float e3 = expx(acc[mt][nt][3]);
                if (rA == cg)     e0 = 0.f;
                if (rA == cg + 1) e1 = 0.f;
                if (rB == cg)     e2 = 0.f;
                if (rB == cg + 1) e3 = 0.f;
                s0 += e0 + e1;
                s1 += e2 + e3;
            }
            rs[mt][0] += s0;
            rs[mt][1] += s1;
        }
    }

    // Reduce over the 4 lanes sharing a row (lane&3), write partials.
#pragma unroll
    for (int mt = 0; mt < 2; mt++)
#pragma unroll
        for (int h = 0; h < 2; h++) {
            float v = rs[mt][h];
            v += __shfl_xor_sync(0xffffffffu, v, 1);
            v += __shfl_xor_sync(0xffffffffu, v, 2);
            if ((lane & 3) == 0) {
                int row = rowBase + wm * 32 + mt * 16 + h * 8 + (lane >> 2);
                g_rowsum[(colHalf * 2 + wn) * N_TOT + row] = v;
            }
        }
}

// ---------------------------------------------------------------------------
// 3) finalize: mean(1/T + ln(S) - pos/T), MUFU lg2
// ---------------------------------------------------------------------------
__global__ void finalize_kernel(float* __restrict__ out) {
    __shared__ float sd[1024];
    int tid = threadIdx.x;
    float acc = 0.f;
    for (int i = tid; i < N_TOT; i += 1024) {
        float S = g_rowsum[i] + g_rowsum[N_TOT + i]
                + g_rowsum[2 * N_TOT + i] + g_rowsum[3 * N_TOT + i];
        float l;
        asm("lg2.approx.f32 %0, %1;" : "=f"(l) : "f"(S));
        acc += INV_T + LN2 * l - g_pos[i & (B_ROWS - 1)] * INV_T;
    }
    sd[tid] = acc;
    __syncthreads();
    for (int o = 512; o > 0; o >>= 1) {
        if (tid < o) sd[tid] += sd[tid + o];
        __syncthreads();
    }
    if (tid == 0) out[0] = sd[0] * (1.0f / (float)N_TOT);
}

// ---------------------------------------------------------------------------
extern "C" void kernel_launch(void* const* d_in, const int* in_sizes, int n_in,
                              void* d_out, int out_size) {
    (void)in_sizes; (void)n_in; (void)out_size;
    const float* zi = (const float*)d_in[0];
    const float* zj = (const float*)d_in[1];

    cudaFuncSetAttribute(sim_kernel, cudaFuncAttributeMaxDynamicSharedMemorySize,
                         SMEM_REQ);
    norm_pos_kernel<<<512, 256>>>(zi, zj);
    sim_kernel<<<dim3(64, 2), 256, SMEM_REQ>>>();
    finalize_kernel<<<1, 1024>>>((float*)d_out);
}

// round 5
// speedup vs baseline: 13.2855x; 1.4478x over previous
#include <cuda_runtime.h>
#include <cuda_bf16.h>
#include <cstdint>

#define B_ROWS 4096
#define N_TOT  8192
#define D_DIM  256
#define INV_T  14.285714285714285714f
#define LOG2E  1.44269504088896340736f
#define LN2    0.69314718055994530942f
#define C1F    (INV_T * LOG2E)

// ---------------- device scratch (no allocs allowed) ----------------
__device__ __nv_bfloat16 g_zn[N_TOT * D_DIM];   // normalized rows, bf16, 4MB
__device__ float g_pos[B_ROWS];
__device__ float g_row[4 * N_TOT];              // rowsum partials [h*2+wn]
__device__ float g_col[128 * N_TOT];            // colsum partials [(d-1)*4+wm]
__device__ float g_part[64];                    // finalize stage-1 partials

// ---------------- PTX helpers (compute_100-safe only) ----------------
__device__ __forceinline__ uint32_t smem_u32(const void* p) {
    uint32_t a;
    asm("{ .reg .u64 t; cvta.to.shared.u64 t, %1; cvt.u32.u64 %0, t; }" : "=r"(a) : "l"(p));
    return a;
}
#define CP_ASYNC_CG(sm, gp) \
    asm volatile("cp.async.cg.shared.global [%0], [%1], 16;" :: "r"(sm), "l"(gp))
#define CP_COMMIT()   asm volatile("cp.async.commit_group;" ::: "memory")
#define CP_WAIT_ALL() asm volatile("cp.async.wait_group 0;" ::: "memory")

#define LDSM_X4(r0, r1, r2, r3, addr) \
    asm volatile("ldmatrix.sync.aligned.m8n8.x4.shared.b16 {%0,%1,%2,%3}, [%4];" \
                 : "=r"(r0), "=r"(r1), "=r"(r2), "=r"(r3) : "r"(addr))

__device__ __forceinline__ void mma_bf16(float* c, uint32_t a0, uint32_t a1,
                                         uint32_t a2, uint32_t a3,
                                         uint32_t b0, uint32_t b1) {
    asm volatile(
        "mma.sync.aligned.m16n8k16.row.col.f32.bf16.bf16.f32 "
        "{%0,%1,%2,%3}, {%4,%5,%6,%7}, {%8,%9}, {%0,%1,%2,%3};"
        : "+f"(c[0]), "+f"(c[1]), "+f"(c[2]), "+f"(c[3])
        : "r"(a0), "r"(a1), "r"(a2), "r"(a3), "r"(b0), "r"(b1));
}

__device__ __forceinline__ float expx(float d) {
    float x = fmaf(d, C1F, -C1F);
    float e;
    asm("ex2.approx.f32 %0, %1;" : "=f"(e) : "f"(x));
    return e;
}

// ---------------------------------------------------------------------------
// 1) Fused normalize + pos
// ---------------------------------------------------------------------------
__global__ void norm_pos_kernel(const float* __restrict__ zi,
                                const float* __restrict__ zj) {
    int w = (blockIdx.x * blockDim.x + threadIdx.x) >> 5;
    int lane = threadIdx.x & 31;
    if (w >= B_ROWS) return;
    const float4* pa = (const float4*)(zi + (size_t)w * D_DIM);
    const float4* pb = (const float4*)(zj + (size_t)w * D_DIM);
    float4 a0 = pa[lane * 2], a1 = pa[lane * 2 + 1];
    float4 b0 = pb[lane * 2], b1 = pb[lane * 2 + 1];
    float sa = a0.x*a0.x + a0.y*a0.y + a0.z*a0.z + a0.w*a0.w
             + a1.x*a1.x + a1.y*a1.y + a1.z*a1.z + a1.w*a1.w;
    float sb = b0.x*b0.x + b0.y*b0.y + b0.z*b0.z + b0.w*b0.w
             + b1.x*b1.x + b1.y*b1.y + b1.z*b1.z + b1.w*b1.w;
    float sd = a0.x*b0.x + a0.y*b0.y + a0.z*b0.z + a0.w*b0.w
             + a1.x*b1.x + a1.y*b1.y + a1.z*b1.z + a1.w*b1.w;
#pragma unroll
    for (int off = 16; off > 0; off >>= 1) {
        sa += __shfl_xor_sync(0xffffffffu, sa, off);
        sb += __shfl_xor_sync(0xffffffffu, sb, off);
        sd += __shfl_xor_sync(0xffffffffu, sd, off);
    }
    float ia = rsqrtf(sa), ib = rsqrtf(sb);
    if (lane == 0) g_pos[w] = sd * ia * ib;

    uint32_t* da = (uint32_t*)(g_zn + (size_t)w * D_DIM);
    uint32_t* db = (uint32_t*)(g_zn + (size_t)(w + B_ROWS) * D_DIM);
    __nv_bfloat162 t;
    t = __floats2bfloat162_rn(a0.x*ia, a0.y*ia); da[lane*4+0] = *(uint32_t*)&t;
    t = __floats2bfloat162_rn(a0.z*ia, a0.w*ia); da[lane*4+1] = *(uint32_t*)&t;
    t = __floats2bfloat162_rn(a1.x*ia, a1.y*ia); da[lane*4+2] = *(uint32_t*)&t;
    t = __floats2bfloat162_rn(a1.z*ia, a1.w*ia); da[lane*4+3] = *(uint32_t*)&t;
    t = __floats2bfloat162_rn(b0.x*ib, b0.y*ib); db[lane*4+0] = *(uint32_t*)&t;
    t = __floats2bfloat162_rn(b0.z*ib, b0.w*ib); db[lane*4+1] = *(uint32_t*)&t;
    t = __floats2bfloat162_rn(b1.x*ib, b1.y*ib); db[lane*4+2] = *(uint32_t*)&t;
    t = __floats2bfloat162_rn(b1.z*ib, b1.w*ib); db[lane*4+3] = *(uint32_t*)&t;
}

// ---------------------------------------------------------------------------
// 2) Symmetric fused warp-MMA GEMM + exp + row/col sums.
// CTA (r, h): A block r resident; tiles d = 16h..16h+15 (+32 if h==1, r<32).
// SMEM: A[64KB] | B0[64KB] | B1[64KB], SW128 XOR swizzle, 128B rows.
// ---------------------------------------------------------------------------
#define A_OFF    0u
#define B0_OFF   65536u
#define B1_OFF   131072u
#define SMEM_REQ 196608

__device__ __forceinline__ void load_tile256(int rowG, uint32_t dst, int tid) {
#pragma unroll
    for (int p = 0; p < 16; p++) {
        int i = tid + p * 256;
        int chunk = i >> 10, rem = i & 1023, row = rem >> 3, seg = rem & 7;
        const __nv_bfloat16* g = g_zn + (size_t)(rowG + row) * D_DIM + chunk * 64 + seg * 8;
        uint32_t soff = (uint32_t)(row * 128 + seg * 16);
        soff ^= (soff >> 3) & 0x70;
        CP_ASYNC_CG(dst + chunk * 16384u + soff, g);
    }
}

__global__ void __launch_bounds__(256, 1) sim_kernel() {
    extern __shared__ char dsm[];
    const uint32_t sbase = smem_u32(dsm);
    const uint32_t sA = sbase + A_OFF;
    const uint32_t sB[2] = { sbase + B0_OFF, sbase + B1_OFF };

    const int tid = threadIdx.x, wid = tid >> 5, lane = tid & 31;
    const int wm = wid & 3, wn = wid >> 2;            // 4 x 2 warp grid
    const int r = blockIdx.x >> 1;                    // row block 0..63
    const int h = blockIdx.x & 1;                     // d-range half
    const int rowBase = r * 128;
    const int nT = 16 + ((h == 1 && r < 32) ? 1 : 0);

    const int mat = lane >> 3, rowIn = lane & 7;
    const int rsel = (mat & 1) << 3;
    const int ksel = (mat >> 1) << 3;

    const int mA0 = wm * 32 + rsel + rowIn;
    const int nB0 = wn * 64 + rsel + rowIn;
    uint32_t aBase[2], aSw[2], bBase[4], bSw[4];
#pragma unroll
    for (int mt = 0; mt < 2; mt++) {
        int m = mA0 + mt * 16;
        aBase[mt] = sA + (uint32_t)(m * 128);
        aSw[mt] = (uint32_t)((m & 7) << 4);
    }
#pragma unroll
    for (int nt = 0; nt < 4; nt++) {
        int n = nB0 + nt * 16;
        bBase[nt] = (uint32_t)(n * 128);
        bSw[nt] = (uint32_t)((n & 7) << 4);
    }

    const int d0 = 16 * h;
    load_tile256(rowBase, sA, tid);
    load_tile256((((r + d0) & 63) * 128), sB[0], tid);
    CP_COMMIT();

    float rs[2][2] = {{0.f, 0.f}, {0.f, 0.f}};

#pragma unroll 1
    for (int t = 0; t < nT; t++) {
        const int buf = t & 1;
        const int d = (t < 16) ? (d0 + t) : 32;
        const int c = (r + d) & 63;
        CP_WAIT_ALL();
        __syncthreads();
        if (t + 1 < nT) {
            const int dn = (t + 1 < 16) ? (d0 + t + 1) : 32;
            load_tile256((((r + dn) & 63) * 128), sB[buf ^ 1], tid);
            CP_COMMIT();
        }

        float acc[2][8][4];
#pragma unroll
        for (int i = 0; i < 2; i++)
#pragma unroll
            for (int j = 0; j < 8; j++)
#pragma unroll
                for (int q = 0; q < 4; q++) acc[i][j][q] = 0.f;

        const uint32_t sBt = sB[buf];
#pragma unroll
        for (int ks = 0; ks < 16; ks++) {
            const uint32_t chunkOff = (uint32_t)(ks >> 2) * 16384u;
            const uint32_t kb = (uint32_t)(((ks & 3) * 16 + ksel) * 2);
            uint32_t a[2][4];
#pragma unroll
            for (int mt = 0; mt < 2; mt++)
                LDSM_X4(a[mt][0], a[mt][1], a[mt][2], a[mt][3],
                        aBase[mt] + chunkOff + (kb ^ aSw[mt]));
#pragma unroll
            for (int nt = 0; nt < 4; nt++) {
                uint32_t b0, b1, b2, b3;
                LDSM_X4(b0, b1, b2, b3,
                        sBt + bBase[nt] + chunkOff + (kb ^ bSw[nt]));
#pragma unroll
                for (int mt = 0; mt < 2; mt++) {
                    mma_bf16(acc[mt][2 * nt],     a[mt][0], a[mt][1], a[mt][2], a[mt][3], b0, b2);
                    mma_bf16(acc[mt][2 * nt + 1], a[mt][0], a[mt][1], a[mt][2], a[mt][3], b1, b3);
                }
            }
        }

        // Epilogue: exp, mask diagonal, rowsums (regs) + colsums (butterfly).
        const int colT = c * 128 + wn * 64;
        const int rA0 = rowBase + wm * 32 + (lane >> 2);
        float colp[16];
#pragma unroll
        for (int q = 0; q < 16; q++) colp[q] = 0.f;

#pragma unroll
        for (int mt = 0; mt < 2; mt++) {
            const int rA = rA0 + mt * 16;
            const int rB = rA + 8;
            float s0 = 0.f, s1 = 0.f;
#pragma unroll
            for (int nt = 0; nt < 8; nt++) {
                const int cg = colT + nt * 8 + ((lane & 3) << 1);
                float e0 = expx(acc[mt][nt][0]);
                float e1 = expx(acc[mt][nt][1]);
                float e2 = expx(acc[mt][nt][2]);
                float e3 = expx(acc[mt][nt][3]);
                if (rA == cg)     e0 = 0.f;
                if (rA == cg + 1) e1 = 0.f;
                if (rB == cg)     e2 = 0.f;
                if (rB == cg + 1) e3 = 0.f;
                s0 += e0 + e1;
                s1 += e2 + e3;
                colp[nt * 2]     += e0 + e2;
                colp[nt * 2 + 1] += e1 + e3;
            }
            rs[mt][0] += s0;
            rs[mt][1] += s1;
        }

        if (d != 0) {
            // reduce colp over the 8 row-groups; butterfly leaves total in all lanes
#pragma unroll
            for (int off = 4; off <= 16; off <<= 1)
#pragma unroll
                for (int q = 0; q < 16; q++)
                    colp[q] += __shfl_xor_sync(0xffffffffu, colp[q], off);
            const int j = lane >> 2;
            float2 v = make_float2(colp[j * 2], colp[j * 2 + 1]);
            int cg0 = colT + j * 8 + ((lane & 3) << 1);
            *(float2*)&g_col[(size_t)((d - 1) * 4 + wm) * N_TOT + cg0] = v;
        }
    }

    // Store register rowsums (4 lanes sharing a row reduce first).
#pragma unroll
    for (int mt = 0; mt < 2; mt++)
#pragma unroll
        for (int hh = 0; hh < 2; hh++) {
            float v = rs[mt][hh];
            v += __shfl_xor_sync(0xffffffffu, v, 1);
            v += __shfl_xor_sync(0xffffffffu, v, 2);
            if ((lane & 3) == 0) {
                int row = rowBase + wm * 32 + mt * 16 + hh * 8 + (lane >> 2);
                g_row[(h * 2 + wn) * N_TOT + row] = v;
            }
        }
}

// ---------------------------------------------------------------------------
// 3) finalize stage 1: per-row S from 4 + 128 partials, per-row term, block sum
// ---------------------------------------------------------------------------
__global__ void finalize1_kernel() {
    __shared__ float sd[128];
    const int tid = threadIdx.x;
    const int row = blockIdx.x * 128 + tid;
    float S = 0.f;
#pragma unroll
    for (int s = 0; s < 4; s++) S += g_row[s * N_TOT + row];
#pragma unroll 8
    for (int s = 0; s < 128; s++) S += g_col[s * N_TOT + row];
    float l;
    asm("lg2.approx.f32 %0, %1;" : "=f"(l) : "f"(S));
    float term = INV_T + LN2 * l - g_pos[row & (B_ROWS - 1)] * INV_T;
    sd[tid] = term;
    __syncthreads();
    for (int o = 64; o > 0; o >>= 1) {
        if (tid < o) sd[tid] += sd[tid + o];
        __syncthreads();
    }
    if (tid == 0) g_part[blockIdx.x] = sd[0];
}

// stage 2: 64 partials -> scalar (all shuffles executed warp-uniformly)
__global__ void finalize2_kernel(float* __restrict__ out) {
    __shared__ float s2[2];
    int tid = threadIdx.x;
    float v = g_part[tid];
#pragma unroll
    for (int off = 16; off > 0; off >>= 1)
        v += __shfl_xor_sync(0xffffffffu, v, off);
    if ((tid & 31) == 0) s2[tid >> 5] = v;
    __syncthreads();
    if (tid == 0) out[0] = (s2[0] + s2[1]) * (1.0f / (float)N_TOT);
}

// ---------------------------------------------------------------------------
extern "C" void kernel_launch(void* const* d_in, const int* in_sizes, int n_in,
                              void* d_out, int out_size) {
    (void)in_sizes; (void)n_in; (void)out_size;
    const float* zi = (const float*)d_in[0];
    const float* zj = (const float*)d_in[1];

    cudaFuncSetAttribute(sim_kernel, cudaFuncAttributeMaxDynamicSharedMemorySize,
                         SMEM_REQ);
    norm_pos_kernel<<<512, 256>>>(zi, zj);
    sim_kernel<<<128, 256, SMEM_REQ>>>();
    finalize1_kernel<<<64, 128>>>();
    finalize2_kernel<<<1, 64>>>((float*)d_out);
}

// round 6
// speedup vs baseline: 13.7155x; 1.0324x over previous
#include <cuda_runtime.h>
#include <cuda_bf16.h>
#include <cstdint>

#define B_ROWS 4096
#define N_TOT  8192
#define D_DIM  256
#define INV_T  14.285714285714285714f
#define LOG2E  1.44269504088896340736f
#define LN2    0.69314718055994530942f
#define C1F    (INV_T * LOG2E)

// ---------------- device scratch (no allocs allowed) ----------------
__device__ __nv_bfloat16 g_zn[N_TOT * D_DIM];   // normalized rows, bf16, 4MB
__device__ float g_pos[B_ROWS];
__device__ float g_row[8 * N_TOT];              // rowsum partials [h*4+wn]
__device__ float g_col[128 * N_TOT];            // colsum partials [(d-1)*4+wm]
__device__ float g_part[64];                    // finalize block partials
__device__ unsigned int g_cnt;                  // finalize last-block counter

// ---------------- PTX helpers (compute_100-safe only) ----------------
__device__ __forceinline__ uint32_t smem_u32(const void* p) {
    uint32_t a;
    asm("{ .reg .u64 t; cvta.to.shared.u64 t, %1; cvt.u32.u64 %0, t; }" : "=r"(a) : "l"(p));
    return a;
}
#define CP_ASYNC_CG(sm, gp) \
    asm volatile("cp.async.cg.shared.global [%0], [%1], 16;" :: "r"(sm), "l"(gp))
#define CP_COMMIT()   asm volatile("cp.async.commit_group;" ::: "memory")
#define CP_WAIT_ALL() asm volatile("cp.async.wait_group 0;" ::: "memory")

#define LDSM_X4(r0, r1, r2, r3, addr) \
    asm volatile("ldmatrix.sync.aligned.m8n8.x4.shared.b16 {%0,%1,%2,%3}, [%4];" \
                 : "=r"(r0), "=r"(r1), "=r"(r2), "=r"(r3) : "r"(addr))

__device__ __forceinline__ void mma_bf16(float* c, uint32_t a0, uint32_t a1,
                                         uint32_t a2, uint32_t a3,
                                         uint32_t b0, uint32_t b1) {
    asm volatile(
        "mma.sync.aligned.m16n8k16.row.col.f32.bf16.bf16.f32 "
        "{%0,%1,%2,%3}, {%4,%5,%6,%7}, {%8,%9}, {%0,%1,%2,%3};"
        : "+f"(c[0]), "+f"(c[1]), "+f"(c[2]), "+f"(c[3])
        : "r"(a0), "r"(a1), "r"(a2), "r"(a3), "r"(b0), "r"(b1));
}

__device__ __forceinline__ float expx(float d) {
    float x = fmaf(d, C1F, -C1F);
    float e;
    asm("ex2.approx.f32 %0, %1;" : "=f"(e) : "f"(x));
    return e;
}

// ---------------------------------------------------------------------------
// 1) Fused normalize + pos
// ---------------------------------------------------------------------------
__global__ void norm_pos_kernel(const float* __restrict__ zi,
                                const float* __restrict__ zj) {
    int w = (blockIdx.x * blockDim.x + threadIdx.x) >> 5;
    int lane = threadIdx.x & 31;
    if (w >= B_ROWS) return;
    const float4* pa = (const float4*)(zi + (size_t)w * D_DIM);
    const float4* pb = (const float4*)(zj + (size_t)w * D_DIM);
    float4 a0 = pa[lane * 2], a1 = pa[lane * 2 + 1];
    float4 b0 = pb[lane * 2], b1 = pb[lane * 2 + 1];
    float sa = a0.x*a0.x + a0.y*a0.y + a0.z*a0.z + a0.w*a0.w
             + a1.x*a1.x + a1.y*a1.y + a1.z*a1.z + a1.w*a1.w;
    float sb = b0.x*b0.x + b0.y*b0.y + b0.z*b0.z + b0.w*b0.w
             + b1.x*b1.x + b1.y*b1.y + b1.z*b1.z + b1.w*b1.w;
    float sd = a0.x*b0.x + a0.y*b0.y + a0.z*b0.z + a0.w*b0.w
             + a1.x*b1.x + a1.y*b1.y + a1.z*b1.z + a1.w*b1.w;
#pragma unroll
    for (int off = 16; off > 0; off >>= 1) {
        sa += __shfl_xor_sync(0xffffffffu, sa, off);
        sb += __shfl_xor_sync(0xffffffffu, sb, off);
        sd += __shfl_xor_sync(0xffffffffu, sd, off);
    }
    float ia = rsqrtf(sa), ib = rsqrtf(sb);
    if (lane == 0) g_pos[w] = sd * ia * ib;

    uint32_t* da = (uint32_t*)(g_zn + (size_t)w * D_DIM);
    uint32_t* db = (uint32_t*)(g_zn + (size_t)(w + B_ROWS) * D_DIM);
    __nv_bfloat162 t;
    t = __floats2bfloat162_rn(a0.x*ia, a0.y*ia); da[lane*4+0] = *(uint32_t*)&t;
    t = __floats2bfloat162_rn(a0.z*ia, a0.w*ia); da[lane*4+1] = *(uint32_t*)&t;
    t = __floats2bfloat162_rn(a1.x*ia, a1.y*ia); da[lane*4+2] = *(uint32_t*)&t;
    t = __floats2bfloat162_rn(a1.z*ia, a1.w*ia); da[lane*4+3] = *(uint32_t*)&t;
    t = __floats2bfloat162_rn(b0.x*ib, b0.y*ib); db[lane*4+0] = *(uint32_t*)&t;
    t = __floats2bfloat162_rn(b0.z*ib, b0.w*ib); db[lane*4+1] = *(uint32_t*)&t;
    t = __floats2bfloat162_rn(b1.x*ib, b1.y*ib); db[lane*4+2] = *(uint32_t*)&t;
    t = __floats2bfloat162_rn(b1.z*ib, b1.w*ib); db[lane*4+3] = *(uint32_t*)&t;
}

// ---------------------------------------------------------------------------
// 2) Symmetric fused warp-MMA GEMM + exp + row/col sums. 512 threads.
// CTA (r, h): A block r resident; tiles d = 16h..16h+15 (+32 if h==1, r<32).
// Warp grid 4(m) x 4(n): warp tile 32m x 32n of the 128x128 output tile.
// SMEM: A[64KB] | B0[64KB] | B1[64KB], SW128 XOR swizzle, 128B rows.
// ---------------------------------------------------------------------------
#define A_OFF    0u
#define B0_OFF   65536u
#define B1_OFF   131072u
#define SMEM_REQ 196608

__device__ __forceinline__ void load_tile512(int rowG, uint32_t dst, int tid) {
#pragma unroll
    for (int p = 0; p < 8; p++) {
        int i = tid + p * 512;
        int chunk = i >> 10, rem = i & 1023, row = rem >> 3, seg = rem & 7;
        const __nv_bfloat16* g = g_zn + (size_t)(rowG + row) * D_DIM + chunk * 64 + seg * 8;
        uint32_t soff = (uint32_t)(row * 128 + seg * 16);
        soff ^= (soff >> 3) & 0x70;
        CP_ASYNC_CG(dst + chunk * 16384u + soff, g);
    }
}

__global__ void __launch_bounds__(512, 1) sim_kernel() {
    extern __shared__ char dsm[];
    const uint32_t sbase = smem_u32(dsm);
    const uint32_t sA = sbase + A_OFF;
    const uint32_t sB[2] = { sbase + B0_OFF, sbase + B1_OFF };

    const int tid = threadIdx.x, wid = tid >> 5, lane = tid & 31;
    const int wm = wid & 3, wn = wid >> 2;            // 4 x 4 warp grid
    const int r = blockIdx.x >> 1;                    // row block 0..63
    const int h = blockIdx.x & 1;                     // d-range half
    const int rowBase = r * 128;
    const int nT = 16 + ((h == 1 && r < 32) ? 1 : 0);

    const int mat = lane >> 3, rowIn = lane & 7;
    const int rsel = (mat & 1) << 3;
    const int ksel = (mat >> 1) << 3;

    const int mA0 = wm * 32 + rsel + rowIn;           // + mt*16
    const int nB0 = wn * 32 + rsel + rowIn;           // + nt*16
    uint32_t aBase[2], aSw[2], bBase[2], bSw[2];
#pragma unroll
    for (int mt = 0; mt < 2; mt++) {
        int m = mA0 + mt * 16;
        aBase[mt] = sA + (uint32_t)(m * 128);
        aSw[mt] = (uint32_t)((m & 7) << 4);
    }
#pragma unroll
    for (int nt = 0; nt < 2; nt++) {
        int n = nB0 + nt * 16;
        bBase[nt] = (uint32_t)(n * 128);
        bSw[nt] = (uint32_t)((n & 7) << 4);
    }

    const int d0 = 16 * h;
    load_tile512(rowBase, sA, tid);
    load_tile512((((r + d0) & 63) * 128), sB[0], tid);
    CP_COMMIT();

    float rs[2][2] = {{0.f, 0.f}, {0.f, 0.f}};

#pragma unroll 1
    for (int t = 0; t < nT; t++) {
        const int buf = t & 1;
        const int d = (t < 16) ? (d0 + t) : 32;
        const int c = (r + d) & 63;
        CP_WAIT_ALL();
        __syncthreads();
        if (t + 1 < nT) {
            const int dn = (t + 1 < 16) ? (d0 + t + 1) : 32;
            load_tile512((((r + dn) & 63) * 128), sB[buf ^ 1], tid);
            CP_COMMIT();
        }

        float acc[2][4][4];
#pragma unroll
        for (int i = 0; i < 2; i++)
#pragma unroll
            for (int j = 0; j < 4; j++)
#pragma unroll
                for (int q = 0; q < 4; q++) acc[i][j][q] = 0.f;

        const uint32_t sBt = sB[buf];
#pragma unroll
        for (int ks = 0; ks < 16; ks++) {
            const uint32_t chunkOff = (uint32_t)(ks >> 2) * 16384u;
            const uint32_t kb = (uint32_t)(((ks & 3) * 16 + ksel) * 2);
            uint32_t a[2][4];
#pragma unroll
            for (int mt = 0; mt < 2; mt++)
                LDSM_X4(a[mt][0], a[mt][1], a[mt][2], a[mt][3],
                        aBase[mt] + chunkOff + (kb ^ aSw[mt]));
#pragma unroll
            for (int nt = 0; nt < 2; nt++) {
                uint32_t b0, b1, b2, b3;
                LDSM_X4(b0, b1, b2, b3,
                        sBt + bBase[nt] + chunkOff + (kb ^ bSw[nt]));
                // b r0:n0-7/k0-7, r1:n8-15/k0-7, r2:n0-7/k8-15, r3:n8-15/k8-15
#pragma unroll
                for (int mt = 0; mt < 2; mt++) {
                    mma_bf16(acc[mt][2 * nt],     a[mt][0], a[mt][1], a[mt][2], a[mt][3], b0, b2);
                    mma_bf16(acc[mt][2 * nt + 1], a[mt][0], a[mt][1], a[mt][2], a[mt][3], b1, b3);
                }
            }
        }

        // Epilogue: exp, mask diagonal, rowsums (regs) + colsums (butterfly).
        const int colT = c * 128 + wn * 32;
        const int rA0 = rowBase + wm * 32 + (lane >> 2);
        float colp[8];
#pragma unroll
        for (int q = 0; q < 8; q++) colp[q] = 0.f;

#pragma unroll
        for (int mt = 0; mt < 2; mt++) {
            const int rA = rA0 + mt * 16;
            const int rB = rA + 8;
            float s0 = 0.f, s1 = 0.f;
#pragma unroll
            for (int ng = 0; ng < 4; ng++) {
                const int cg = colT + ng * 8 + ((lane & 3) << 1);
                float e0 = expx(acc[mt][ng][0]);
                float e1 = expx(acc[mt][ng][1]);
                float e2 = expx(acc[mt][ng][2]);
                float e3 = expx(acc[mt][ng][3]);
                if (rA == cg)     e0 = 0.f;
                if (rA == cg + 1) e1 = 0.f;
                if (rB == cg)     e2 = 0.f;
                if (rB == cg + 1) e3 = 0.f;
                s0 += e0 + e1;
                s1 += e2 + e3;
                colp[ng * 2]     += e0 + e2;
                colp[ng * 2 + 1] += e1 + e3;
            }
            rs[mt][0] += s0;
            rs[mt][1] += s1;
        }

        if (d != 0) {
            // reduce colp over the 8 row-groups; butterfly leaves totals everywhere
#pragma unroll
            for (int off = 4; off <= 16; off <<= 1)
#pragma unroll
                for (int q = 0; q < 8; q++)
                    colp[q] += __shfl_xor_sync(0xffffffffu, colp[q], off);
            // lanes with (lane>>2)=j < 4 write col pair j (32 cols per warp)
            const int j = lane >> 2;
            if (j < 4) {
                float2 v = make_float2(colp[j * 2], colp[j * 2 + 1]);
                int cg0 = colT + j * 8 + ((lane & 3) << 1);
                *(float2*)&g_col[(size_t)((d - 1) * 4 + wm) * N_TOT + cg0] = v;
            }
        }
    }

    // Store register rowsums (4 lanes sharing a row reduce first).
#pragma unroll
    for (int mt = 0; mt < 2; mt++)
#pragma unroll
        for (int hh = 0; hh < 2; hh++) {
            float v = rs[mt][hh];
            v += __shfl_xor_sync(0xffffffffu, v, 1);
            v += __shfl_xor_sync(0xffffffffu, v, 2);
            if ((lane & 3) == 0) {
                int row = rowBase + wm * 32 + mt * 16 + hh * 8 + (lane >> 2);
                g_row[(h * 4 + wn) * N_TOT + row] = v;
            }
        }
}

// ---------------------------------------------------------------------------
// 3) finalize (single kernel, last-block reduction, graph-replay-safe)
// ---------------------------------------------------------------------------
__global__ void finalize_kernel(float* __restrict__ out) {
    __shared__ float sd[128];
    __shared__ bool amLast;
    const int tid = threadIdx.x;
    const int row = blockIdx.x * 128 + tid;
    float S = 0.f;
#pragma unroll
    for (int s = 0; s < 8; s++) S += g_row[s * N_TOT + row];
#pragma unroll 8
    for (int s = 0; s < 128; s++) S += g_col[s * N_TOT + row];
    float l;
    asm("lg2.approx.f32 %0, %1;" : "=f"(l) : "f"(S));
    float term = INV_T + LN2 * l - g_pos[row & (B_ROWS - 1)] * INV_T;
    sd[tid] = term;
    __syncthreads();
    for (int o = 64; o > 0; o >>= 1) {
        if (tid < o) sd[tid] += sd[tid + o];
        __syncthreads();
    }
    if (tid == 0) {
        g_part[blockIdx.x] = sd[0];
        __threadfence();
        unsigned int prev = atomicAdd(&g_cnt, 1u);
        amLast = (prev == 63u);
    }
    __syncthreads();
    if (amLast) {
        // full warp executes uniformly; lanes 32..127 idle via tid<32 guard on data
        if (tid < 32) {
            float v = g_part[tid] + g_part[tid + 32];
#pragma unroll
            for (int off = 16; off > 0; off >>= 1)
                v += __shfl_xor_sync(0xffffffffu, v, off);
            if (tid == 0) {
                out[0] = v * (1.0f / (float)N_TOT);
                g_cnt = 0u;   // reset for next graph replay
            }
        }
    }
}

// ---------------------------------------------------------------------------
extern "C" void kernel_launch(void* const* d_in, const int* in_sizes, int n_in,
                              void* d_out, int out_size) {
    (void)in_sizes; (void)n_in; (void)out_size;
    const float* zi = (const float*)d_in[0];
    const float* zj = (const float*)d_in[1];

    cudaFuncSetAttribute(sim_kernel, cudaFuncAttributeMaxDynamicSharedMemorySize,
                         SMEM_REQ);
    norm_pos_kernel<<<512, 256>>>(zi, zj);
    sim_kernel<<<128, 512, SMEM_REQ>>>();
    finalize_kernel<<<64, 128>>>((float*)d_out);
}